// round 5
// baseline (speedup 1.0000x reference)
#include <cuda_runtime.h>
#include <math.h>
#include <stdint.h>

// Problem constants
#define V_SIZE 50257
#define B_SIZE 8
#define S_SIZE 512
#define NUM_DRAFTS 4
#define DRAFT_LEN 8
#define NROWS 256                         // K*L*B = 4*8*8
#define NCHUNKS 8                         // argmax chunks per row
#define CHUNK_SZ ((V_SIZE + NCHUNKS - 1) / NCHUNKS)
#define ARGMAX_BLOCKS (NCHUNKS * NROWS)   // 2048

// threefry2x32 key for jax.random.key(42): (0, 42)
#define TF_KS0 0u
#define TF_KS1 42u
#define TF_KS2 (0x1BD11BDAu ^ TF_KS0 ^ TF_KS1)

// Scratch (device globals; allocations are forbidden)
__device__ float g_sumpart[B_SIZE][NCHUNKS];   // partial exp-sums (from rows 0..7)
__device__ float g_pE[NROWS * NCHUNKS];        // per-(row,chunk) best numerator
__device__ float g_pe[NROWS * NCHUNKS];        // per-(row,chunk) best denominator
__device__ int   g_pi[NROWS * NCHUNKS];        // per-(row,chunk) best index

__device__ __forceinline__ void tf_round(uint32_t &x0, uint32_t &x1, int r) {
    x0 += x1;
    x1 = __funnelshift_l(x1, x1, r);
    x1 ^= x0;
}

// Partitionable threefry random_bits (32-bit): counter i (< 2^32) ->
// threefry2x32(key=(0,42), x0=0, x1=i), folded o.x ^ o.y.
__device__ __forceinline__ uint32_t tf_bits32(uint32_t i) {
    uint32_t x0 = TF_KS0, x1 = i + TF_KS1;
    tf_round(x0,x1,13); tf_round(x0,x1,15); tf_round(x0,x1,26); tf_round(x0,x1,6);
    x0 += TF_KS1; x1 += TF_KS2 + 1u;
    tf_round(x0,x1,17); tf_round(x0,x1,29); tf_round(x0,x1,16); tf_round(x0,x1,24);
    x0 += TF_KS2; x1 += TF_KS0 + 2u;
    tf_round(x0,x1,13); tf_round(x0,x1,15); tf_round(x0,x1,26); tf_round(x0,x1,6);
    x0 += TF_KS0; x1 += TF_KS1 + 3u;
    tf_round(x0,x1,17); tf_round(x0,x1,29); tf_round(x0,x1,16); tf_round(x0,x1,24);
    x0 += TF_KS1; x1 += TF_KS2 + 4u;
    tf_round(x0,x1,13); tf_round(x0,x1,15); tf_round(x0,x1,26); tf_round(x0,x1,6);
    x0 += TF_KS2; x1 += TF_KS0 + 5u;
    return x0 ^ x1;
}

// ---------------------------------------------------------------------------
// Fused kernel: 2048 blocks; block (c, r) does gumbel-argmax for row r over
// vocab chunk c. Blocks with r < 8 additionally accumulate the softmax
// denominator (they already compute E for every v in their chunk).
//
// Argmax math: score(v) = E_v/e_v with E = exp(lv) (via __expf: uniform
// ~8e-7 relative error, ordering-safe) and e = -log(u) via ACCURATE logf
// (MUFU.LG2 is catastrophically inaccurate near u->1, which is where argmax
// winners live -- proven by the round-4 failure). Best kept as a fraction
// (bestE, beste); cross-multiply compare, no division in the hot loop.
// ---------------------------------------------------------------------------
__global__ void __launch_bounds__(256) spec_fused_kernel(const float* __restrict__ logits) {
    const int blk = blockIdx.x;
    const int t = threadIdx.x;
    const int r = blk & 255;               // flattened (k,l,b); b = r & 7
    const int c = blk >> 8;                // chunk 0..7
    const int b = r & 7;
    const bool do_sum = (r < B_SIZE);
    const float* __restrict__ last = logits + ((size_t)b * S_SIZE + (S_SIZE - 1)) * V_SIZE;

    const int begin = c * CHUNK_SZ;
    const int end   = min(V_SIZE, begin + CHUNK_SZ);
    const uint32_t base = (uint32_t)r * (uint32_t)V_SIZE;

    float bestE = 0.0f, beste = 1.0f;      // score 0: any real candidate beats it
    int idx = 0;
    float acc = 0.0f;                      // softmax partial (rows 0..7 only)

    #pragma unroll 4
    for (int v = begin + t; v < end; v += 256) {
        uint32_t bits = tf_bits32(base + (uint32_t)v);
        float f = __uint_as_float((bits >> 9) | 0x3f800000u) - 1.0f;
        float u = fmaxf(f, 1.17549435e-38f);        // jax uniform(minval=tiny)
        float e = -logf(u);                         // ACCURATE log (ordering-critical)
        float E = __expf(__ldg(last + v));          // FMUL + MUFU.EX2 (safe)
        if (do_sum) acc += E;
        // ascending v with strict >: first max wins (jnp.argmax tie rule)
        if (E * beste > bestE * e) { bestE = E; beste = e; idx = v; }
    }

    __shared__ float sE[256];
    __shared__ float se[256];
    __shared__ int   si[256];
    __shared__ float sa[256];
    sE[t] = bestE; se[t] = beste; si[t] = idx; sa[t] = acc;
    __syncthreads();
    for (int s = 128; s; s >>= 1) {
        if (t < s) {
            float a = sE[t + s] * se[t];
            float d = sE[t] * se[t + s];
            // strictly better, or exact tie with smaller index
            if (a > d || (a == d && si[t + s] < si[t])) {
                sE[t] = sE[t + s]; se[t] = se[t + s]; si[t] = si[t + s];
            }
            sa[t] += sa[t + s];
        }
        __syncthreads();
    }
    if (t == 0) {
        int slot = r * NCHUNKS + c;
        g_pE[slot] = sE[0];
        g_pe[slot] = se[0];
        g_pi[slot] = si[0];
        if (do_sum) g_sumpart[b][c] = sa[0];
    }
}

// ---------------------------------------------------------------------------
// Finalize: 1 block x 256 threads; t enumerates (b,k,l) in draft_tokens
// output order b*32 + k*8 + l.
// Output layout (float32, concatenated tuple, 808 elements):
//   [0,256)   draft_tokens  (B,K,L)
//   [256,512) draft_probs
//   [512,768) accepted_mask (0/1)
//   [768,800) acceptance_ratio (B,K)
//   [800,808) best_draft_idx (B)
// ---------------------------------------------------------------------------
__global__ void spec_finalize_kernel(const float* __restrict__ logits,
                                     float* __restrict__ out) {
    int t = threadIdx.x;
    int b = t >> 5;
    int k = (t >> 3) & 3;
    int l = t & 7;
    int row = ((k * DRAFT_LEN + l) << 3) + b;   // flattened (k,l,b)

    // per-batch exp-sum
    __shared__ float smsum[B_SIZE];
    if (t < B_SIZE) {
        float s = 0.0f;
        #pragma unroll
        for (int c = 0; c < NCHUNKS; c++) s += g_sumpart[t][c];
        smsum[t] = s;
    }

    // combine the 8 chunk partials of this row (chunks are ascending idx
    // ranges; strict > keeps the earliest chunk on exact ties)
    float bestE = g_pE[row * NCHUNKS];
    float beste = g_pe[row * NCHUNKS];
    int   tok   = g_pi[row * NCHUNKS];
    #pragma unroll
    for (int c = 1; c < NCHUNKS; c++) {
        float E2 = g_pE[row * NCHUNKS + c];
        float e2 = g_pe[row * NCHUNKS + c];
        if (E2 * beste > bestE * e2) {
            bestE = E2; beste = e2; tok = g_pi[row * NCHUNKS + c];
        }
    }
    __syncthreads();

    const float* last = logits + ((size_t)b * S_SIZE + (S_SIZE - 1)) * V_SIZE;
    float p = __expf(__ldg(last + tok)) / smsum[b];   // 8e-7 rel err << 1e-3 tol
    float m = (p >= 0.8f) ? 1.0f : 0.0f;

    out[t]       = (float)tok;   // token ids < 2^24: exact in f32
    out[256 + t] = p;
    out[512 + t] = m;

    __shared__ float sp[256];
    __shared__ float sm[256];
    __shared__ float meanp[32];
    sp[t] = p; sm[t] = m;
    __syncthreads();

    if ((t & 7) == 0) {
        float ps = 0.0f, ms = 0.0f;
        #pragma unroll
        for (int i = 0; i < 8; i++) { ps += sp[t + i]; ms += sm[t + i]; }
        int bk = t >> 3;                 // = b*4 + k
        out[768 + bk] = ms * 0.125f;     // acceptance_ratio
        meanp[bk] = ps;                  // scale irrelevant to argmax
    }
    __syncthreads();

    if (t < B_SIZE) {
        float bv = meanp[t * 4];
        int bi = 0;
        #pragma unroll
        for (int kk = 1; kk < 4; kk++) {
            float vv = meanp[t * 4 + kk];
            if (vv > bv) { bv = vv; bi = kk; }   // strict >: first max wins
        }
        out[800 + t] = (float)bi;
    }
}

extern "C" void kernel_launch(void* const* d_in, const int* in_sizes, int n_in,
                              void* d_out, int out_size) {
    // metadata order: hidden_states, logits, verifier_logits.
    // Only logits[:, -1, :] is live in the reference.
    const float* logits = (const float*)d_in[1];
    float* out = (float*)d_out;

    spec_fused_kernel<<<ARGMAX_BLOCKS, 256>>>(logits);
    spec_finalize_kernel<<<1, 256>>>(logits, out);
}

// round 6
// speedup vs baseline: 1.0354x; 1.0354x over previous
#include <cuda_runtime.h>
#include <math.h>
#include <stdint.h>

// Problem constants
#define V_SIZE 50257
#define B_SIZE 8
#define S_SIZE 512
#define NUM_DRAFTS 4
#define DRAFT_LEN 8
#define NROWS 256                         // K*L*B = 4*8*8
#define NCHUNKS 4                         // argmax chunks per row
#define CHUNK_SZ ((V_SIZE + NCHUNKS - 1) / NCHUNKS)
#define GRID_BLOCKS (NCHUNKS * NROWS)     // 1024

// threefry2x32 key for jax.random.key(42): (0, 42)
#define TF_KS0 0u
#define TF_KS1 42u
#define TF_KS2 (0x1BD11BDAu ^ TF_KS0 ^ TF_KS1)

// Scratch (device globals; allocations are forbidden)
__device__ float g_sumpart[B_SIZE][NCHUNKS];   // partial exp-sums (rows 0..7)
__device__ float g_pE[NROWS * NCHUNKS];        // per-(row,chunk) best numerator
__device__ float g_pe[NROWS * NCHUNKS];        // per-(row,chunk) best denominator
__device__ int   g_pi[NROWS * NCHUNKS];        // per-(row,chunk) best index
__device__ unsigned int g_done;                // arrival counter (reset by last block)

__device__ __forceinline__ void tf_round(uint32_t &x0, uint32_t &x1, int r) {
    x0 += x1;
    x1 = __funnelshift_l(x1, x1, r);
    x1 ^= x0;
}

// Partitionable threefry random_bits (32-bit): counter i (< 2^32) ->
// threefry2x32(key=(0,42), x0=0, x1=i), folded o.x ^ o.y.
__device__ __forceinline__ uint32_t tf_bits32(uint32_t i) {
    uint32_t x0 = TF_KS0, x1 = i + TF_KS1;
    tf_round(x0,x1,13); tf_round(x0,x1,15); tf_round(x0,x1,26); tf_round(x0,x1,6);
    x0 += TF_KS1; x1 += TF_KS2 + 1u;
    tf_round(x0,x1,17); tf_round(x0,x1,29); tf_round(x0,x1,16); tf_round(x0,x1,24);
    x0 += TF_KS2; x1 += TF_KS0 + 2u;
    tf_round(x0,x1,13); tf_round(x0,x1,15); tf_round(x0,x1,26); tf_round(x0,x1,6);
    x0 += TF_KS0; x1 += TF_KS1 + 3u;
    tf_round(x0,x1,17); tf_round(x0,x1,29); tf_round(x0,x1,16); tf_round(x0,x1,24);
    x0 += TF_KS1; x1 += TF_KS2 + 4u;
    tf_round(x0,x1,13); tf_round(x0,x1,15); tf_round(x0,x1,26); tf_round(x0,x1,6);
    x0 += TF_KS2; x1 += TF_KS0 + 5u;
    return x0 ^ x1;
}

// ---------------------------------------------------------------------------
// Single fused kernel: 1024 blocks; block (c, r) does gumbel-argmax for row r
// over vocab chunk c. Blocks with r < 8 also accumulate the softmax
// denominator. The LAST block to finish (atomic ticket) inlines the finalize.
//
// Argmax math: score(v) = E_v/e_v with E = __expf(lv) (uniform ~8e-7 rel err,
// ordering-safe) and e = -logf(u) ACCURATE (MUFU.LG2 is catastrophically
// inaccurate near u->1 where argmax winners live -- round-4 failure). Best is
// a fraction (bestE, beste); cross-multiply compare, no division in the loop.
// ---------------------------------------------------------------------------
__global__ void __launch_bounds__(256) spec_fused_kernel(const float* __restrict__ logits,
                                                         float* __restrict__ out) {
    const int blk = blockIdx.x;
    const int t = threadIdx.x;
    const int r = blk & 255;               // flattened (k,l,b); b = r & 7
    const int c = blk >> 8;                // chunk 0..NCHUNKS-1
    const int b = r & 7;
    const bool do_sum = (r < B_SIZE);
    const float* __restrict__ last = logits + ((size_t)b * S_SIZE + (S_SIZE - 1)) * V_SIZE;

    const int begin = c * CHUNK_SZ;
    const int end   = min(V_SIZE, begin + CHUNK_SZ);
    const uint32_t base = (uint32_t)r * (uint32_t)V_SIZE;

    float bestE = 0.0f, beste = 1.0f;      // score 0: any real candidate beats it
    int idx = 0;
    float acc = 0.0f;

    #pragma unroll 4
    for (int v = begin + t; v < end; v += 256) {
        uint32_t bits = tf_bits32(base + (uint32_t)v);
        float f = __uint_as_float((bits >> 9) | 0x3f800000u) - 1.0f;
        float u = fmaxf(f, 1.17549435e-38f);        // jax uniform(minval=tiny)
        float e = -logf(u);                         // ACCURATE log (ordering-critical)
        float E = __expf(__ldg(last + v));          // FMUL + MUFU.EX2 (safe)
        if (do_sum) acc += E;
        // ascending v with strict >: first max wins (jnp.argmax tie rule)
        if (E * beste > bestE * e) { bestE = E; beste = e; idx = v; }
    }

    // ---- warp-level reduction (no __syncthreads rounds) ----
    const unsigned FULL = 0xFFFFFFFFu;
    #pragma unroll
    for (int off = 16; off; off >>= 1) {
        float E2 = __shfl_down_sync(FULL, bestE, off);
        float e2 = __shfl_down_sync(FULL, beste, off);
        int   i2 = __shfl_down_sync(FULL, idx,   off);
        float a = E2 * beste;
        float d = bestE * e2;
        if (a > d || (a == d && i2 < idx)) { bestE = E2; beste = e2; idx = i2; }
        acc += __shfl_down_sync(FULL, acc, off);
    }

    __shared__ float wE[8], we[8], wa[8];
    __shared__ int   wi[8];
    if ((t & 31) == 0) {
        int w = t >> 5;
        wE[w] = bestE; we[w] = beste; wi[w] = idx; wa[w] = acc;
    }
    __syncthreads();

    if (t == 0) {
        float bE = wE[0], be = we[0], ba = wa[0];
        int bi = wi[0];
        #pragma unroll
        for (int w = 1; w < 8; w++) {
            float a = wE[w] * be;
            float d = bE * we[w];
            if (a > d || (a == d && wi[w] < bi)) { bE = wE[w]; be = we[w]; bi = wi[w]; }
            ba += wa[w];
        }
        int slot = r * NCHUNKS + c;
        g_pE[slot] = bE;
        g_pe[slot] = be;
        g_pi[slot] = bi;
        if (do_sum) g_sumpart[b][c] = ba;
    }

    // ---- last-block-done: inline finalize ----
    __shared__ bool isLast;
    __threadfence();
    if (t == 0) {
        unsigned int ticket = atomicAdd(&g_done, 1u);
        isLast = (ticket == GRID_BLOCKS - 1);
        if (isLast) g_done = 0;            // reset for next graph replay
    }
    __syncthreads();
    if (!isLast) return;

    // === finalize (one block, 256 threads) ===
    // t enumerates (b,k,l) in draft_tokens output order b*32 + k*8 + l.
    // Output layout (float32, 808 elements):
    //   [0,256) tokens  [256,512) probs  [512,768) mask
    //   [768,800) acceptance_ratio (B,K)  [800,808) best_draft_idx (B)
    {
        int fb = t >> 5;
        int row = (((((t >> 3) & 3) * DRAFT_LEN) + (t & 7)) << 3) + fb;  // (k,l,b)

        __shared__ float smsum[B_SIZE];
        if (t < B_SIZE) {
            float s = 0.0f;
            #pragma unroll
            for (int cc = 0; cc < NCHUNKS; cc++) s += g_sumpart[t][cc];
            smsum[t] = s;
        }

        // combine chunk partials (ascending idx ranges; strict > keeps earliest)
        float bE = g_pE[row * NCHUNKS];
        float be = g_pe[row * NCHUNKS];
        int  tok = g_pi[row * NCHUNKS];
        #pragma unroll
        for (int cc = 1; cc < NCHUNKS; cc++) {
            float E2 = g_pE[row * NCHUNKS + cc];
            float e2 = g_pe[row * NCHUNKS + cc];
            if (E2 * be > bE * e2) { bE = E2; be = e2; tok = g_pi[row * NCHUNKS + cc]; }
        }
        __syncthreads();

        const float* lastb = logits + ((size_t)fb * S_SIZE + (S_SIZE - 1)) * V_SIZE;
        float p = __expf(__ldg(lastb + tok)) / smsum[fb];  // 8e-7 rel << 1e-3 tol
        float m = (p >= 0.8f) ? 1.0f : 0.0f;

        out[t]       = (float)tok;   // token ids < 2^24: exact in f32
        out[256 + t] = p;
        out[512 + t] = m;

        __shared__ float sp[256];
        __shared__ float sm[256];
        __shared__ float meanp[32];
        sp[t] = p; sm[t] = m;
        __syncthreads();

        if ((t & 7) == 0) {
            float ps = 0.0f, ms = 0.0f;
            #pragma unroll
            for (int i = 0; i < 8; i++) { ps += sp[t + i]; ms += sm[t + i]; }
            int bk = t >> 3;                 // = b*4 + k
            out[768 + bk] = ms * 0.125f;     // acceptance_ratio
            meanp[bk] = ps;                  // scale irrelevant to argmax
        }
        __syncthreads();

        if (t < B_SIZE) {
            float bv = meanp[t * 4];
            int bi2 = 0;
            #pragma unroll
            for (int kk = 1; kk < 4; kk++) {
                float vv = meanp[t * 4 + kk];
                if (vv > bv) { bv = vv; bi2 = kk; }   // strict >: first max wins
            }
            out[800 + t] = (float)bi2;
        }
    }
}

extern "C" void kernel_launch(void* const* d_in, const int* in_sizes, int n_in,
                              void* d_out, int out_size) {
    // metadata order: hidden_states, logits, verifier_logits.
    // Only logits[:, -1, :] is live in the reference.
    const float* logits = (const float*)d_in[1];
    float* out = (float*)d_out;

    spec_fused_kernel<<<GRID_BLOCKS, 256>>>(logits, out);
}

// round 7
// speedup vs baseline: 1.0935x; 1.0561x over previous
#include <cuda_runtime.h>
#include <math.h>
#include <stdint.h>

// Problem constants
#define V_SIZE 50257
#define B_SIZE 8
#define S_SIZE 512
#define NUM_DRAFTS 4
#define DRAFT_LEN 8
#define NROWS 256                         // K*L*B = 4*8*8
#define NCHUNKS 6                         // argmax chunks per row
#define CHUNK_SZ ((V_SIZE + NCHUNKS - 1) / NCHUNKS)
#define GRID_BLOCKS (NCHUNKS * NROWS)     // 1536

// threefry2x32 key for jax.random.key(42): (0, 42)
#define TF_KS0 0u
#define TF_KS1 42u
#define TF_KS2 (0x1BD11BDAu ^ TF_KS0 ^ TF_KS1)

#define LN2F 0.69314718055994530942f

// Scratch (device globals; allocations are forbidden)
__device__ float g_sumpart[B_SIZE][NCHUNKS];   // partial exp-sums (rows 0..7)
__device__ float g_pE[NROWS * NCHUNKS];        // per-(row,chunk) best numerator
__device__ float g_pe[NROWS * NCHUNKS];        // per-(row,chunk) best denominator
__device__ int   g_pi[NROWS * NCHUNKS];        // per-(row,chunk) best index
__device__ unsigned int g_done;                // arrival counter (reset by last block)

__device__ __forceinline__ void tf_round(uint32_t &x0, uint32_t &x1, int r) {
    x0 += x1;
    x1 = __funnelshift_l(x1, x1, r);
    x1 ^= x0;
}

// Partitionable threefry random_bits (32-bit): counter i (< 2^32) ->
// threefry2x32(key=(0,42), x0=0, x1=i), folded o.x ^ o.y.
__device__ __forceinline__ uint32_t tf_bits32(uint32_t i) {
    uint32_t x0 = TF_KS0, x1 = i + TF_KS1;
    tf_round(x0,x1,13); tf_round(x0,x1,15); tf_round(x0,x1,26); tf_round(x0,x1,6);
    x0 += TF_KS1; x1 += TF_KS2 + 1u;
    tf_round(x0,x1,17); tf_round(x0,x1,29); tf_round(x0,x1,16); tf_round(x0,x1,24);
    x0 += TF_KS2; x1 += TF_KS0 + 2u;
    tf_round(x0,x1,13); tf_round(x0,x1,15); tf_round(x0,x1,26); tf_round(x0,x1,6);
    x0 += TF_KS0; x1 += TF_KS1 + 3u;
    tf_round(x0,x1,17); tf_round(x0,x1,29); tf_round(x0,x1,16); tf_round(x0,x1,24);
    x0 += TF_KS1; x1 += TF_KS2 + 4u;
    tf_round(x0,x1,13); tf_round(x0,x1,15); tf_round(x0,x1,26); tf_round(x0,x1,6);
    x0 += TF_KS2; x1 += TF_KS0 + 5u;
    return x0 ^ x1;
}

// e = -log(u) with everywhere-small RELATIVE error, cheaper than logf:
//   d = 1-u.  d < 1/8  -> degree-8 poly of -log1p(-d): rel err <= ~4.5e-7
//             d >= 1/8 -> -ln2*MUFU.LG2(u): e >= 0.133, abs err 1.65e-7
//                         -> rel err <= 1.24e-6.
// (Plain MUFU.LG2 everywhere failed in round 4: rel err blows up as u->1.)
__device__ __forceinline__ float neglog_u(float u) {
    float d = 1.0f - u;                       // Sterbenz-exact for u >= 0.5
    float h = 0.125f;                         // 1/8
    h = __fmaf_rn(h, d, 0.14285715f);         // 1/7
    h = __fmaf_rn(h, d, 0.16666667f);         // 1/6
    h = __fmaf_rn(h, d, 0.2f);                // 1/5
    h = __fmaf_rn(h, d, 0.25f);               // 1/4
    h = __fmaf_rn(h, d, 0.33333334f);         // 1/3
    h = __fmaf_rn(h, d, 0.5f);                // 1/2
    h = __fmaf_rn(h, d, 1.0f);
    float e_poly = h * d;
    float e_mufu = -LN2F * __log2f(u);
    return (d < 0.125f) ? e_poly : e_mufu;
}

// ---------------------------------------------------------------------------
// Single fused kernel: GRID_BLOCKS blocks; block (c, r) does gumbel-argmax for
// row r over vocab chunk c. Blocks with r < 8 also accumulate the softmax
// denominator. The LAST block to finish (atomic ticket) inlines the finalize.
//
// Argmax math: score(v) = E_v/e_v with E = __expf(lv) (uniform ~8e-7 rel err,
// ordering-safe) and e = neglog_u(u) (see above). Best is a fraction
// (bestE, beste); cross-multiply compare, no division in the loop.
// ---------------------------------------------------------------------------
__global__ void __launch_bounds__(256) spec_fused_kernel(const float* __restrict__ logits,
                                                         float* __restrict__ out) {
    const int blk = blockIdx.x;
    const int t = threadIdx.x;
    const int r = blk & 255;               // flattened (k,l,b); b = r & 7
    const int c = blk >> 8;                // chunk 0..NCHUNKS-1
    const int b = r & 7;
    const bool do_sum = (r < B_SIZE);
    const float* __restrict__ last = logits + ((size_t)b * S_SIZE + (S_SIZE - 1)) * V_SIZE;

    const int begin = c * CHUNK_SZ;
    const int end   = min(V_SIZE, begin + CHUNK_SZ);
    const uint32_t base = (uint32_t)r * (uint32_t)V_SIZE;

    float bestE = 0.0f, beste = 1.0f;      // score 0: any real candidate beats it
    int idx = 0;
    float acc = 0.0f;

    if (do_sum) {
        #pragma unroll 4
        for (int v = begin + t; v < end; v += 256) {
            uint32_t bits = tf_bits32(base + (uint32_t)v);
            float f = __uint_as_float((bits >> 9) | 0x3f800000u) - 1.0f;
            float u = fmaxf(f, 1.17549435e-38f);   // jax uniform(minval=tiny)
            float e = neglog_u(u);
            float E = __expf(__ldg(last + v));
            acc += E;
            if (E * beste > bestE * e) { bestE = E; beste = e; idx = v; }
        }
    } else {
        #pragma unroll 4
        for (int v = begin + t; v < end; v += 256) {
            uint32_t bits = tf_bits32(base + (uint32_t)v);
            float f = __uint_as_float((bits >> 9) | 0x3f800000u) - 1.0f;
            float u = fmaxf(f, 1.17549435e-38f);
            float e = neglog_u(u);
            float E = __expf(__ldg(last + v));
            // ascending v with strict >: first max wins (jnp.argmax tie rule)
            if (E * beste > bestE * e) { bestE = E; beste = e; idx = v; }
        }
    }

    // ---- warp-level reduction ----
    const unsigned FULL = 0xFFFFFFFFu;
    #pragma unroll
    for (int off = 16; off; off >>= 1) {
        float E2 = __shfl_down_sync(FULL, bestE, off);
        float e2 = __shfl_down_sync(FULL, beste, off);
        int   i2 = __shfl_down_sync(FULL, idx,   off);
        float a = E2 * beste;
        float d2 = bestE * e2;
        if (a > d2 || (a == d2 && i2 < idx)) { bestE = E2; beste = e2; idx = i2; }
        acc += __shfl_down_sync(FULL, acc, off);
    }

    __shared__ float wE[8], we[8], wa[8];
    __shared__ int   wi[8];
    if ((t & 31) == 0) {
        int w = t >> 5;
        wE[w] = bestE; we[w] = beste; wi[w] = idx; wa[w] = acc;
    }
    __syncthreads();

    if (t == 0) {
        float bE = wE[0], be = we[0], ba = wa[0];
        int bi = wi[0];
        #pragma unroll
        for (int w = 1; w < 8; w++) {
            float a = wE[w] * be;
            float d2 = bE * we[w];
            if (a > d2 || (a == d2 && wi[w] < bi)) { bE = wE[w]; be = we[w]; bi = wi[w]; }
            ba += wa[w];
        }
        int slot = r * NCHUNKS + c;
        g_pE[slot] = bE;
        g_pe[slot] = be;
        g_pi[slot] = bi;
        if (do_sum) g_sumpart[b][c] = ba;
    }

    // ---- last-block-done: inline finalize ----
    __shared__ bool isLast;
    __threadfence();
    if (t == 0) {
        unsigned int ticket = atomicAdd(&g_done, 1u);
        isLast = (ticket == GRID_BLOCKS - 1);
        if (isLast) g_done = 0;            // reset for next graph replay
    }
    __syncthreads();
    if (!isLast) return;

    // === finalize (one block, 256 threads) ===
    // t enumerates (b,k,l) in draft_tokens output order b*32 + k*8 + l.
    // Output layout (float32, 808 elements):
    //   [0,256) tokens  [256,512) probs  [512,768) mask
    //   [768,800) acceptance_ratio (B,K)  [800,808) best_draft_idx (B)
    {
        int fb = t >> 5;
        int row = (((((t >> 3) & 3) * DRAFT_LEN) + (t & 7)) << 3) + fb;  // (k,l,b)

        __shared__ float smsum[B_SIZE];
        if (t < B_SIZE) {
            float s = 0.0f;
            #pragma unroll
            for (int cc = 0; cc < NCHUNKS; cc++) s += g_sumpart[t][cc];
            smsum[t] = s;
        }

        // combine chunk partials (ascending idx ranges; strict > keeps earliest)
        float bE = g_pE[row * NCHUNKS];
        float be = g_pe[row * NCHUNKS];
        int  tok = g_pi[row * NCHUNKS];
        #pragma unroll
        for (int cc = 1; cc < NCHUNKS; cc++) {
            float E2 = g_pE[row * NCHUNKS + cc];
            float e2 = g_pe[row * NCHUNKS + cc];
            if (E2 * be > bE * e2) { bE = E2; be = e2; tok = g_pi[row * NCHUNKS + cc]; }
        }
        __syncthreads();

        const float* lastb = logits + ((size_t)fb * S_SIZE + (S_SIZE - 1)) * V_SIZE;
        float p = __expf(__ldg(lastb + tok)) / smsum[fb];  // 8e-7 rel << 1e-3 tol
        float m = (p >= 0.8f) ? 1.0f : 0.0f;

        out[t]       = (float)tok;   // token ids < 2^24: exact in f32
        out[256 + t] = p;
        out[512 + t] = m;

        __shared__ float sp[256];
        __shared__ float sm[256];
        __shared__ float meanp[32];
        sp[t] = p; sm[t] = m;
        __syncthreads();

        if ((t & 7) == 0) {
            float ps = 0.0f, ms = 0.0f;
            #pragma unroll
            for (int i = 0; i < 8; i++) { ps += sp[t + i]; ms += sm[t + i]; }
            int bk = t >> 3;                 // = b*4 + k
            out[768 + bk] = ms * 0.125f;     // acceptance_ratio
            meanp[bk] = ps;                  // scale irrelevant to argmax
        }
        __syncthreads();

        if (t < B_SIZE) {
            float bv = meanp[t * 4];
            int bi2 = 0;
            #pragma unroll
            for (int kk = 1; kk < 4; kk++) {
                float vv = meanp[t * 4 + kk];
                if (vv > bv) { bv = vv; bi2 = kk; }   // strict >: first max wins
            }
            out[800 + t] = (float)bi2;
        }
    }
}

extern "C" void kernel_launch(void* const* d_in, const int* in_sizes, int n_in,
                              void* d_out, int out_size) {
    // metadata order: hidden_states, logits, verifier_logits.
    // Only logits[:, -1, :] is live in the reference.
    const float* logits = (const float*)d_in[1];
    float* out = (float*)d_out;

    spec_fused_kernel<<<GRID_BLOCKS, 256>>>(logits, out);
}